// round 1
// baseline (speedup 1.0000x reference)
#include <cuda_runtime.h>
#include <cuda_bf16.h>

// Packed f32x2 FMA (Blackwell sm_100+ only; ptxas never emits this from C++).
#define FMA_F32X2(d, a, b, c) \
    asm("fma.rn.f32x2 %0, %1, %2, %3;" : "=l"(d) : "l"(a), "l"(b), "l"(c))
#define PACK_F32X2(out, lo, hi) \
    asm("mov.b64 %0, {%1, %2};" : "=l"(out) \
        : "r"(__float_as_uint(lo)), "r"(__float_as_uint(hi)))

static constexpr int BATCH = 16;
static constexpr int C     = 64;    // CIN == COUT
static constexpr int HW    = 112;
static constexpr int TS    = 16;    // output tile h and w per block
static constexpr int CC    = 8;     // CIN chunk per smem pass
static constexpr int WS    = 20;    // smem input row stride (floats) — conflict-free layout
static constexpr int PLANE = 18 * WS;  // 360 floats per channel plane (18 rows w/ halo)

__global__ __launch_bounds__(256, 2)
void conv3x3_f32x2_kernel(const float* __restrict__ x,
                          const float* __restrict__ wt,
                          const float* __restrict__ bias,
                          float* __restrict__ out)
{
    __shared__ float s_in[CC * PLANE];      // 2880 floats
    __shared__ float s_w[CC * 9 * 64];      // 4608 floats

    const int tid  = threadIdx.x;
    const int lane = tid & 31;
    const int cg   = tid >> 5;       // warp id 0..7 -> cout group (warp-uniform)
    const int hh   = lane & 15;      // output row within tile
    const int wsg  = lane >> 4;      // 0/1 -> w segment
    const int w_off = wsg * 8;

    const int w0 = blockIdx.x * TS;
    const int h0 = blockIdx.y * TS;
    const int b  = blockIdx.z;

    // acc[i][j]: packed pair {out[ch0+2i][w_off+j], out[ch0+2i+1][w_off+j]}
    unsigned long long acc[4][8];
    #pragma unroll
    for (int i = 0; i < 4; ++i)
        #pragma unroll
        for (int j = 0; j < 8; ++j) acc[i][j] = 0ull;

    #pragma unroll 1
    for (int cc = 0; cc < C / CC; ++cc) {
        const int c0 = cc * CC;

        // ---- load weights chunk: rows (c0*9 .. c0*9+72) x 64 couts, contiguous ----
        {
            const float4* src = (const float4*)(wt + (size_t)c0 * 9 * 64);
            float4* dst = (float4*)s_w;
            #pragma unroll
            for (int i = 0; i < 5; ++i) {
                int idx = tid + i * 256;
                if (idx < (CC * 9 * 64) / 4) dst[idx] = src[idx];
            }
        }
        // ---- load input tile with halo: CC x 18 x 18 (zero padded) ----
        {
            #pragma unroll
            for (int i = 0; i < 11; ++i) {
                int idx = tid + i * 256;
                if (idx < CC * 18 * 18) {
                    int cl  = idx / 324;
                    int rem = idx - cl * 324;
                    int r   = rem / 18;
                    int cp  = rem - r * 18;
                    int gh  = h0 - 1 + r;
                    int gw  = w0 - 1 + cp;
                    float v = 0.f;
                    if ((unsigned)gh < HW && (unsigned)gw < HW)
                        v = x[((((size_t)b * C) + (c0 + cl)) * HW + gh) * HW + gw];
                    s_in[cl * PLANE + r * WS + cp] = v;
                }
            }
        }
        __syncthreads();

        // ---- compute ----
        #pragma unroll 4
        for (int cl = 0; cl < CC; ++cl) {
            const float* ip = s_in + cl * PLANE + w_off;
            #pragma unroll
            for (int kh = 0; kh < 3; ++kh) {
                const float* row = ip + (hh + kh) * WS;
                float4 a0 = *(const float4*)(row);
                float4 a1 = *(const float4*)(row + 4);
                float2 a2 = *(const float2*)(row + 8);
                float win[10] = {a0.x, a0.y, a0.z, a0.w,
                                 a1.x, a1.y, a1.z, a1.w,
                                 a2.x, a2.y};
                unsigned long long p[10];
                #pragma unroll
                for (int j = 0; j < 10; ++j) PACK_F32X2(p[j], win[j], win[j]);

                #pragma unroll
                for (int kw = 0; kw < 3; ++kw) {
                    // 8 consecutive couts, read as 4 packed pairs (32B aligned)
                    const ulonglong2* wp = (const ulonglong2*)
                        (s_w + ((cl * 9 + kh * 3 + kw) * 64 + cg * 8));
                    ulonglong2 q0 = wp[0];
                    ulonglong2 q1 = wp[1];
                    unsigned long long wq[4] = {q0.x, q0.y, q1.x, q1.y};
                    #pragma unroll
                    for (int i = 0; i < 4; ++i)
                        #pragma unroll
                        for (int j = 0; j < 8; ++j)
                            FMA_F32X2(acc[i][j], p[j + kw], wq[i], acc[i][j]);
                }
            }
        }
        __syncthreads();
    }

    // ---- epilogue: unpack, add bias, store ----
    const int h = h0 + hh;
    #pragma unroll
    for (int i = 0; i < 4; ++i) {
        const int ch0 = cg * 8 + 2 * i;
        const float b0 = __ldg(bias + ch0);
        const float b1 = __ldg(bias + ch0 + 1);
        float r0[8], r1[8];
        #pragma unroll
        for (int j = 0; j < 8; ++j) {
            unsigned int lo, hi;
            asm("mov.b64 {%0, %1}, %2;" : "=r"(lo), "=r"(hi) : "l"(acc[i][j]));
            r0[j] = __uint_as_float(lo) + b0;
            r1[j] = __uint_as_float(hi) + b1;
        }
        float* o0 = out + ((((size_t)b * C) + ch0) * HW + h) * HW + w0 + w_off;
        float* o1 = o0 + (size_t)HW * HW;
        *(float4*)(o0)     = make_float4(r0[0], r0[1], r0[2], r0[3]);
        *(float4*)(o0 + 4) = make_float4(r0[4], r0[5], r0[6], r0[7]);
        *(float4*)(o1)     = make_float4(r1[0], r1[1], r1[2], r1[3]);
        *(float4*)(o1 + 4) = make_float4(r1[4], r1[5], r1[6], r1[7]);
    }
}

extern "C" void kernel_launch(void* const* d_in, const int* in_sizes, int n_in,
                              void* d_out, int out_size)
{
    const float* x    = (const float*)d_in[0];
    const float* wt   = (const float*)d_in[1];
    const float* bias = (const float*)d_in[2];
    float* out = (float*)d_out;

    dim3 grid(HW / TS, HW / TS, BATCH);   // 7 x 7 x 16
    conv3x3_f32x2_kernel<<<grid, 256>>>(x, wt, bias, out);
}

// round 2
// speedup vs baseline: 1.0066x; 1.0066x over previous
#include <cuda_runtime.h>
#include <cuda_bf16.h>

// Packed f32x2 FMA (Blackwell sm_100+ only; ptxas never emits this from C++).
#define FMA_F32X2(d, a, b, c) \
    asm("fma.rn.f32x2 %0, %1, %2, %3;" : "=l"(d) : "l"(a), "l"(b), "l"(c))
#define PACK_F32X2(out, lo, hi) \
    asm("mov.b64 %0, {%1, %2};" : "=l"(out) \
        : "r"(__float_as_uint(lo)), "r"(__float_as_uint(hi)))

static constexpr int BATCH = 16;
static constexpr int C     = 64;    // CIN == COUT
static constexpr int HW    = 112;
static constexpr int TS    = 16;    // output tile h and w per block
static constexpr int CC    = 8;     // CIN chunk per smem pass
static constexpr int WS    = 20;    // smem input row stride (floats) — conflict-free layout
static constexpr int PLANE = 18 * WS;  // 360 floats per channel plane (18 rows w/ halo)

__global__ __launch_bounds__(256, 2)
void conv3x3_f32x2_kernel(const float* __restrict__ x,
                          const float* __restrict__ wt,
                          const float* __restrict__ bias,
                          float* __restrict__ out)
{
    __shared__ float s_in[CC * PLANE];      // 2880 floats
    __shared__ float s_w[CC * 9 * 64];      // 4608 floats

    const int tid  = threadIdx.x;
    const int lane = tid & 31;
    const int cg   = tid >> 5;       // warp id 0..7 -> cout group (warp-uniform)
    const int hh   = lane & 15;      // output row within tile
    const int wsg  = lane >> 4;      // 0/1 -> w segment
    const int w_off = wsg * 8;

    const int w0 = blockIdx.x * TS;
    const int h0 = blockIdx.y * TS;
    const int b  = blockIdx.z;

    // acc[i][j]: packed pair {out[ch0+2i][w_off+j], out[ch0+2i+1][w_off+j]}
    unsigned long long acc[4][8];
    #pragma unroll
    for (int i = 0; i < 4; ++i)
        #pragma unroll
        for (int j = 0; j < 8; ++j) acc[i][j] = 0ull;

    #pragma unroll 1
    for (int cc = 0; cc < C / CC; ++cc) {
        const int c0 = cc * CC;

        // ---- load weights chunk: rows (c0*9 .. c0*9+72) x 64 couts, contiguous ----
        {
            const float4* src = (const float4*)(wt + (size_t)c0 * 9 * 64);
            float4* dst = (float4*)s_w;
            #pragma unroll
            for (int i = 0; i < 5; ++i) {
                int idx = tid + i * 256;
                if (idx < (CC * 9 * 64) / 4) dst[idx] = src[idx];
            }
        }
        // ---- load input tile with halo: CC x 18 x 18 (zero padded) ----
        {
            #pragma unroll
            for (int i = 0; i < 11; ++i) {
                int idx = tid + i * 256;
                if (idx < CC * 18 * 18) {
                    int cl  = idx / 324;
                    int rem = idx - cl * 324;
                    int r   = rem / 18;
                    int cp  = rem - r * 18;
                    int gh  = h0 - 1 + r;
                    int gw  = w0 - 1 + cp;
                    float v = 0.f;
                    if ((unsigned)gh < HW && (unsigned)gw < HW)
                        v = x[((((size_t)b * C) + (c0 + cl)) * HW + gh) * HW + gw];
                    s_in[cl * PLANE + r * WS + cp] = v;
                }
            }
        }
        __syncthreads();

        // ---- compute ----
        #pragma unroll 4
        for (int cl = 0; cl < CC; ++cl) {
            const float* ip = s_in + cl * PLANE + w_off;
            #pragma unroll
            for (int kh = 0; kh < 3; ++kh) {
                const float* row = ip + (hh + kh) * WS;
                float4 a0 = *(const float4*)(row);
                float4 a1 = *(const float4*)(row + 4);
                float2 a2 = *(const float2*)(row + 8);
                float win[10] = {a0.x, a0.y, a0.z, a0.w,
                                 a1.x, a1.y, a1.z, a1.w,
                                 a2.x, a2.y};
                unsigned long long p[10];
                #pragma unroll
                for (int j = 0; j < 10; ++j) PACK_F32X2(p[j], win[j], win[j]);

                #pragma unroll
                for (int kw = 0; kw < 3; ++kw) {
                    // 8 consecutive couts, read as 4 packed pairs (32B aligned)
                    const ulonglong2* wp = (const ulonglong2*)
                        (s_w + ((cl * 9 + kh * 3 + kw) * 64 + cg * 8));
                    ulonglong2 q0 = wp[0];
                    ulonglong2 q1 = wp[1];
                    unsigned long long wq[4] = {q0.x, q0.y, q1.x, q1.y};
                    #pragma unroll
                    for (int i = 0; i < 4; ++i)
                        #pragma unroll
                        for (int j = 0; j < 8; ++j)
                            FMA_F32X2(acc[i][j], p[j + kw], wq[i], acc[i][j]);
                }
            }
        }
        __syncthreads();
    }

    // ---- epilogue: unpack, add bias, store ----
    const int h = h0 + hh;
    #pragma unroll
    for (int i = 0; i < 4; ++i) {
        const int ch0 = cg * 8 + 2 * i;
        const float b0 = __ldg(bias + ch0);
        const float b1 = __ldg(bias + ch0 + 1);
        float r0[8], r1[8];
        #pragma unroll
        for (int j = 0; j < 8; ++j) {
            unsigned int lo, hi;
            asm("mov.b64 {%0, %1}, %2;" : "=r"(lo), "=r"(hi) : "l"(acc[i][j]));
            r0[j] = __uint_as_float(lo) + b0;
            r1[j] = __uint_as_float(hi) + b1;
        }
        float* o0 = out + ((((size_t)b * C) + ch0) * HW + h) * HW + w0 + w_off;
        float* o1 = o0 + (size_t)HW * HW;
        *(float4*)(o0)     = make_float4(r0[0], r0[1], r0[2], r0[3]);
        *(float4*)(o0 + 4) = make_float4(r0[4], r0[5], r0[6], r0[7]);
        *(float4*)(o1)     = make_float4(r1[0], r1[1], r1[2], r1[3]);
        *(float4*)(o1 + 4) = make_float4(r1[4], r1[5], r1[6], r1[7]);
    }
}

extern "C" void kernel_launch(void* const* d_in, const int* in_sizes, int n_in,
                              void* d_out, int out_size)
{
    const float* x    = (const float*)d_in[0];
    const float* wt   = (const float*)d_in[1];
    const float* bias = (const float*)d_in[2];
    float* out = (float*)d_out;

    dim3 grid(HW / TS, HW / TS, BATCH);   // 7 x 7 x 16
    conv3x3_f32x2_kernel<<<grid, 256>>>(x, wt, bias, out);
}

// round 4
// speedup vs baseline: 1.9508x; 1.9379x over previous
#include <cuda_runtime.h>
#include <cstdint>
#include <cstddef>

// ---------------- helpers ----------------
__device__ __forceinline__ uint32_t rnd_tf32(float f) {
    uint32_t r;
    asm("cvt.rna.tf32.f32 %0, %1;" : "=r"(r) : "f"(f));
    return r;
}

// m16n8k8 row.col f32.tf32.tf32.f32  (family-common PTX, works on plain sm_103)
#define MMA_TF32(c, a, b0, b1)                                                  \
    asm volatile("mma.sync.aligned.m16n8k8.row.col.f32.tf32.tf32.f32 "          \
                 "{%0,%1,%2,%3},{%4,%5,%6,%7},{%8,%9},{%0,%1,%2,%3};"           \
                 : "+f"((c)[0]), "+f"((c)[1]), "+f"((c)[2]), "+f"((c)[3])       \
                 : "r"((a)[0]), "r"((a)[1]), "r"((a)[2]), "r"((a)[3]),          \
                   "r"(b0), "r"(b1))

// ---------------- problem constants ----------------
static constexpr int BATCH = 16;
static constexpr int C     = 64;     // CIN == COUT
static constexpr int HW    = 112;
static constexpr int TH    = 16;     // tile h  -> M = 256 pixels per CTA
static constexpr int TW    = 16;     // tile w
static constexpr int RS    = 20;     // halo row stride (floats)
static constexpr int CPL   = 360;    // halo plane stride (floats); 360 % 32 == 8 -> bank-perfect A loads

// dynamic smem (floats): B2 fragment buffer then halo
static constexpr int B2_FLOATS   = 4096;                  // 16384 B
static constexpr int HALO_FLOATS = C * CPL;               // 23040
static constexpr int SMEM_SZ     = (B2_FLOATS + HALO_FLOATS) * 4;   // 108544 B

__global__ void __launch_bounds__(256, 2)
conv3x3_tf32_mma(const float* __restrict__ x,
                 const float* __restrict__ wt,
                 const float* __restrict__ bias,
                 float* __restrict__ out)
{
    extern __shared__ float smem[];
    float* B2   = smem;                 // [s][wn][half][lane] 16B/thread-chunk, frag order
    float* halo = smem + B2_FLOATS;     // [cin][row(20)][col]

    const int tid  = threadIdx.x;
    const int lane = tid & 31;
    const int wid  = tid >> 5;
    const int wm   = wid >> 1;          // 0..3 : 4 h-rows each
    const int wn   = wid & 1;           // 0..1 : 32 couts each
    const int g    = lane >> 2;         // groupID 0..7
    const int t    = lane & 3;          // thread-in-group

    const int w0 = blockIdx.x * TW;
    const int h0 = blockIdx.y * TH;
    const int b  = blockIdx.z;

    // ---- halo load: 64 cin x 18 x 18, tf32-rounded, zero padded ----
    #pragma unroll 4
    for (int i = 0; i < 81; ++i) {      // 81*256 == 64*18*18 exactly
        int idx = tid + i * 256;
        int c   = idx / 324;
        int rem = idx - c * 324;
        int r   = rem / 18;
        int w   = rem - r * 18;
        int gh = h0 - 1 + r, gw = w0 - 1 + w;
        uint32_t v = 0u;
        if ((unsigned)gh < (unsigned)HW && (unsigned)gw < (unsigned)HW)
            v = rnd_tf32(x[(((size_t)b * C + c) * HW + gh) * HW + gw]);
        halo[c * CPL + r * RS + w] = __uint_as_float(v);
    }

    float acc[4][4][4];                 // [mt][nt][creg]
    #pragma unroll
    for (int i = 0; i < 4; ++i)
        #pragma unroll
        for (int j = 0; j < 4; ++j)
            #pragma unroll
            for (int k = 0; k < 4; ++k) acc[i][j][k] = 0.f;

    // builder roles (B staging)
    const int bs = tid >> 5;            // cin slice 0..7
    const int bl = tid & 31;
    const int bt = bl & 3;
    const int bg = bl >> 2;

    #pragma unroll 1
    for (int kpos = 0; kpos < 9; ++kpos) {
        const int kh = kpos / 3;
        const int kw = kpos - kh * 3;

        __syncthreads();   // prior readers of B2 done (also orders halo on iter 0)

        // ---- stage B fragments for this kpos: value pair {W[s8+t][co], W[s8+t+4][co]} ----
        {
            const float* r0 = wt + ((size_t)(bs * 8 + bt)     * 9 + kpos) * 64;
            const float* r1 = wt + ((size_t)(bs * 8 + bt + 4) * 9 + kpos) * 64;
            #pragma unroll
            for (int wnn = 0; wnn < 2; ++wnn)
                #pragma unroll
                for (int nt = 0; nt < 4; ++nt) {
                    int co = wnn * 32 + nt * 8 + bg;
                    float2 v = make_float2(__uint_as_float(rnd_tf32(r0[co])),
                                           __uint_as_float(rnd_tf32(r1[co])));
                    *(float2*)((char*)B2 + (bs * 2 + wnn) * 1024 + (nt >> 1) * 512
                                         + bl * 16 + (nt & 1) * 8) = v;
                }
        }
        __syncthreads();

        // ---- compute: 8 cin-slices of K8 ----
        const char* ab = (const char*)halo
                       + ((size_t)t * CPL + (wm * 4 + kh) * RS + g + kw) * 4;
        const char* bb = (const char*)B2 + wn * 1024 + lane * 16;

        #pragma unroll
        for (int s = 0; s < 8; ++s) {
            uint32_t A[4][4];
            #pragma unroll
            for (int mt = 0; mt < 4; ++mt) {
                const char* p = ab + s * 11520 + mt * 80;   // s*8 planes, mt rows
                A[mt][0] = *(const uint32_t*)(p);           // (g,   t)
                A[mt][1] = *(const uint32_t*)(p + 32);      // (g+8, t)
                A[mt][2] = *(const uint32_t*)(p + 5760);    // (g,   t+4)
                A[mt][3] = *(const uint32_t*)(p + 5792);    // (g+8, t+4)
            }
            uint32_t Bf[8];
            *(uint4*)&Bf[0] = *(const uint4*)(bb + s * 2048);        // nt0, nt1
            *(uint4*)&Bf[4] = *(const uint4*)(bb + s * 2048 + 512);  // nt2, nt3

            #pragma unroll
            for (int mt = 0; mt < 4; ++mt)
                #pragma unroll
                for (int nt = 0; nt < 4; ++nt)
                    MMA_TF32(acc[mt][nt], A[mt], Bf[nt * 2], Bf[nt * 2 + 1]);
        }
    }

    // ---- epilogue ----
    #pragma unroll
    for (int nt = 0; nt < 4; ++nt) {
        const int co0 = wn * 32 + nt * 8 + 2 * t;
        const float bz0 = __ldg(bias + co0);
        const float bz1 = __ldg(bias + co0 + 1);
        #pragma unroll
        for (int mt = 0; mt < 4; ++mt) {
            const int h = h0 + wm * 4 + mt;
            float* p0 = out + (((size_t)b * C + co0) * HW + h) * HW + w0;
            float* p1 = p0 + (size_t)HW * HW;
            p0[g]     = acc[mt][nt][0] + bz0;   // c0: row g,   col 2t
            p1[g]     = acc[mt][nt][1] + bz1;   // c1: row g,   col 2t+1
            p0[g + 8] = acc[mt][nt][2] + bz0;   // c2: row g+8, col 2t
            p1[g + 8] = acc[mt][nt][3] + bz1;   // c3: row g+8, col 2t+1
        }
    }
}

extern "C" void kernel_launch(void* const* d_in, const int* in_sizes, int n_in,
                              void* d_out, int out_size)
{
    const float* x    = (const float*)d_in[0];
    const float* wt   = (const float*)d_in[1];
    const float* bias = (const float*)d_in[2];
    float* out = (float*)d_out;

    cudaFuncSetAttribute(conv3x3_tf32_mma,
                         cudaFuncAttributeMaxDynamicSharedMemorySize, SMEM_SZ);
    dim3 grid(HW / TW, HW / TH, BATCH);   // 7 x 7 x 16
    conv3x3_tf32_mma<<<grid, 256, SMEM_SZ>>>(x, wt, bias, out);
}

// round 5
// speedup vs baseline: 2.2241x; 1.1401x over previous
#include <cuda_runtime.h>
#include <cstdint>
#include <cstddef>

// ---------------- helpers ----------------
__device__ __forceinline__ uint32_t rnd_tf32(float f) {
    uint32_t r;
    asm("cvt.rna.tf32.f32 %0, %1;" : "=r"(r) : "f"(f));
    return r;
}

// m16n8k8 row.col f32.tf32.tf32.f32  (family-common PTX, works on plain sm_103)
#define MMA_TF32(c, a, b0, b1)                                                  \
    asm volatile("mma.sync.aligned.m16n8k8.row.col.f32.tf32.tf32.f32 "          \
                 "{%0,%1,%2,%3},{%4,%5,%6,%7},{%8,%9},{%0,%1,%2,%3};"           \
                 : "+f"((c)[0]), "+f"((c)[1]), "+f"((c)[2]), "+f"((c)[3])       \
                 : "r"((a)[0]), "r"((a)[1]), "r"((a)[2]), "r"((a)[3]),          \
                   "r"(b0), "r"(b1))

// ---------------- problem constants ----------------
static constexpr int BATCH = 16;
static constexpr int C     = 64;     // CIN == COUT
static constexpr int HW    = 112;
static constexpr int TH    = 8;      // tile h  -> M = 128 pixels per CTA
static constexpr int TW    = 16;     // tile w
static constexpr int RS    = 20;     // halo row stride (floats)
static constexpr int CPL   = 200;    // halo plane stride; 200 % 32 == 8 -> bank-perfect A loads

// dynamic smem (floats): B2 fragment buffer then halo
static constexpr int B2_FLOATS   = 4096;                  // 16384 B
static constexpr int HALO_FLOATS = C * CPL;               // 12800
static constexpr int SMEM_SZ     = (B2_FLOATS + HALO_FLOATS) * 4;   // 67584 B

__global__ void __launch_bounds__(256, 3)
conv3x3_tf32_mma(const float* __restrict__ x,
                 const float* __restrict__ wt,
                 const float* __restrict__ bias,
                 float* __restrict__ out)
{
    extern __shared__ float smem[];
    float* B2   = smem;                 // fragment-order weight slices
    float* halo = smem + B2_FLOATS;     // [cin][row(20)][col]

    const int tid  = threadIdx.x;
    const int lane = tid & 31;
    const int wid  = tid >> 5;
    const int wm   = wid >> 1;          // 0..3 : 2 h-rows each
    const int wn   = wid & 1;           // 0..1 : 32 couts each
    const int g    = lane >> 2;         // groupID 0..7
    const int t    = lane & 3;          // thread-in-group

    const int w0 = blockIdx.x * TW;
    const int h0 = blockIdx.y * TH;
    const int b  = blockIdx.z;

    // ---- halo load: 64 cin x 10 x 18, tf32-rounded, zero padded ----
    #pragma unroll 5
    for (int i = 0; i < 45; ++i) {      // 45*256 == 64*10*18 exactly
        int idx = tid + i * 256;
        int c   = idx / 180;
        int rem = idx - c * 180;
        int r   = rem / 18;
        int w   = rem - r * 18;
        int gh = h0 - 1 + r, gw = w0 - 1 + w;
        uint32_t v = 0u;
        if ((unsigned)gh < (unsigned)HW && (unsigned)gw < (unsigned)HW)
            v = rnd_tf32(x[(((size_t)b * C + c) * HW + gh) * HW + gw]);
        halo[c * CPL + r * RS + w] = __uint_as_float(v);
    }

    float acc[2][4][4];                 // [mt][nt][creg]
    #pragma unroll
    for (int i = 0; i < 2; ++i)
        #pragma unroll
        for (int j = 0; j < 4; ++j)
            #pragma unroll
            for (int k = 0; k < 4; ++k) acc[i][j][k] = 0.f;

    // builder roles (B staging)
    const int bs = wid;                 // cin slice 0..7
    const int bt = lane & 3;
    const int bg = lane >> 2;

    #pragma unroll 1
    for (int kpos = 0; kpos < 9; ++kpos) {
        const int kh = kpos / 3;
        const int kw = kpos - kh * 3;

        __syncthreads();   // prior readers of B2 done (also orders halo on iter 0)

        // ---- stage B fragments: value pair {W[8bs+bt][co], W[8bs+bt+4][co]} ----
        {
            const float* r0 = wt + ((size_t)(bs * 8 + bt)     * 9 + kpos) * 64;
            const float* r1 = wt + ((size_t)(bs * 8 + bt + 4) * 9 + kpos) * 64;
            #pragma unroll
            for (int wnn = 0; wnn < 2; ++wnn)
                #pragma unroll
                for (int nt = 0; nt < 4; ++nt) {
                    int co = wnn * 32 + nt * 8 + bg;
                    float2 v = make_float2(__uint_as_float(rnd_tf32(r0[co])),
                                           __uint_as_float(rnd_tf32(r1[co])));
                    *(float2*)((char*)B2 + (bs * 2 + wnn) * 1024 + (nt >> 1) * 512
                                         + lane * 16 + (nt & 1) * 8) = v;
                }
        }
        __syncthreads();

        // ---- compute: 8 cin-slices of K8 ----
        const char* ab = (const char*)halo
                       + ((size_t)t * CPL + (wm * 2 + kh) * RS + g + kw) * 4;
        const char* bb = (const char*)B2 + wn * 1024 + lane * 16;

        #pragma unroll
        for (int s = 0; s < 8; ++s) {
            uint32_t A[2][4];
            #pragma unroll
            for (int mt = 0; mt < 2; ++mt) {
                const char* p = ab + s * 6400 + mt * 80;    // s*8 planes, mt rows
                A[mt][0] = *(const uint32_t*)(p);           // (w=g,   cin=8s+t)
                A[mt][1] = *(const uint32_t*)(p + 32);      // (w=g+8, cin=8s+t)
                A[mt][2] = *(const uint32_t*)(p + 3200);    // (w=g,   cin=8s+t+4)
                A[mt][3] = *(const uint32_t*)(p + 3232);    // (w=g+8, cin=8s+t+4)
            }
            uint32_t Bf[8];
            *(uint4*)&Bf[0] = *(const uint4*)(bb + s * 2048);        // nt0, nt1
            *(uint4*)&Bf[4] = *(const uint4*)(bb + s * 2048 + 512);  // nt2, nt3

            #pragma unroll
            for (int mt = 0; mt < 2; ++mt)
                #pragma unroll
                for (int nt = 0; nt < 4; ++nt)
                    MMA_TF32(acc[mt][nt], A[mt], Bf[nt * 2], Bf[nt * 2 + 1]);
        }
    }

    // ---- epilogue ----
    #pragma unroll
    for (int nt = 0; nt < 4; ++nt) {
        const int co0 = wn * 32 + nt * 8 + 2 * t;
        const float bz0 = __ldg(bias + co0);
        const float bz1 = __ldg(bias + co0 + 1);
        #pragma unroll
        for (int mt = 0; mt < 2; ++mt) {
            const int h = h0 + wm * 2 + mt;
            float* p0 = out + (((size_t)b * C + co0) * HW + h) * HW + w0;
            float* p1 = p0 + (size_t)HW * HW;
            p0[g]     = acc[mt][nt][0] + bz0;   // c0: w=g,   cout co0
            p1[g]     = acc[mt][nt][1] + bz1;   // c1: w=g,   cout co0+1
            p0[g + 8] = acc[mt][nt][2] + bz0;   // c2: w=g+8, cout co0
            p1[g + 8] = acc[mt][nt][3] + bz1;   // c3: w=g+8, cout co0+1
        }
    }
}

extern "C" void kernel_launch(void* const* d_in, const int* in_sizes, int n_in,
                              void* d_out, int out_size)
{
    const float* x    = (const float*)d_in[0];
    const float* wt   = (const float*)d_in[1];
    const float* bias = (const float*)d_in[2];
    float* out = (float*)d_out;

    cudaFuncSetAttribute(conv3x3_tf32_mma,
                         cudaFuncAttributeMaxDynamicSharedMemorySize, SMEM_SZ);
    dim3 grid(HW / TW, HW / TH, BATCH);   // 7 x 14 x 16
    conv3x3_tf32_mma<<<grid, 256, SMEM_SZ>>>(x, wt, bias, out);
}